// round 16
// baseline (speedup 1.0000x reference)
#include <cuda_runtime.h>
#include <math.h>

// Shapes (fixed):
//   root_rvel : (256, 1024, 1, 1)
//   local_pos : (256, 1025, 24, 3)
//   local_rot : (256, 1025, 24, 6)
//   root_vel  : (256, 1024, 1, 2)
// Output: concat(flatten(global_pos), flatten(global_rot))

#define NB   256
#define T    1024
#define TP1  1025
#define J    24
#define TOT2 (NB * TP1 * J)           // 6,297,600
#define PAIRS (TOT2 / 2)              // 3,148,800
#define POS_ELEMS (NB * TP1 * J * 3)  // 18,892,800
#define P2_THREADS 256
#define P2_BLOCKS (PAIRS / P2_THREADS)   // 12300 exactly
#define FIX_CAP 8192

__device__ float2 g_rot[NB * TP1];       // (ch, sh) fast-trig half-angle quat
__device__ float2 g_pos[NB * TP1];       // integrated (px, pz)
__device__ float  g_r[NB * TP1];         // r_excl for the exact rescue
__device__ unsigned int g_fix_count;
__device__ unsigned int g_fix[FIX_CAP];  // flagged item indices

// Plain (non-contracted) fp32 ops to match reference's mul/add/sub/div exactly.
__device__ __forceinline__ float fM(float a, float b) { return __fmul_rn(a, b); }
__device__ __forceinline__ float fA(float a, float b) { return __fadd_rn(a, b); }
__device__ __forceinline__ float fS(float a, float b) { return __fsub_rn(a, b); }
__device__ __forceinline__ float fD(float a, float b) { return __fdiv_rn(a, b); }

// Fast trig (few-ulp): all VALUE computation.
__device__ __forceinline__ void half_cs_fast(float r, float& ch, float& sh) {
    float r2 = __fmul_rn(r, r);
    float an = __fsqrt_rn(r2);
    float half = __fmul_rn(0.5f, an);
    float s, c;
    sincosf(half, &s, &c);
    ch = c;
    if (an < 1e-6f) {
        float k = __fsub_rn(0.5f, __fdiv_rn(__fmul_rn(an, an), 48.0f));
        sh = __fmul_rn(r, k);
    } else {
        float k = __fdiv_rn(s, an);
        sh = __fmul_rn(r, k);
    }
}

// Exact trig (correctly-rounded float via fp64 == reference bits): fixup only.
__device__ __forceinline__ void half_cs_exact(float r, float& ch, float& sh) {
    float r2 = __fmul_rn(r, r);
    float an = __fsqrt_rn(r2);
    float half = __fmul_rn(0.5f, an);
    double sd, cd;
    sincos((double)half, &sd, &cd);
    ch = (float)cd;
    if (an < 1e-6f) {
        float k = __fsub_rn(0.5f, __fdiv_rn(__fmul_rn(an, an), 48.0f));
        sh = __fmul_rn(r, k);
    } else {
        float s32 = (float)sd;
        float k = __fdiv_rn(s32, an);
        sh = __fmul_rn(r, k);
    }
}

// ---------------------------------------------------------------------------
// XLA ReduceWindowRewriter(base_length=16) cumsum order for length 1024.
// ---------------------------------------------------------------------------
__device__ __forceinline__ void rwr16_scan(
    int t, const float* __restrict__ x, float* __restrict__ out,
    float* __restrict__ inn, float* __restrict__ u,
    float* __restrict__ m, float* __restrict__ w)
{
    __syncthreads();
    if (t < 64) {
        float acc = 0.0f;
#pragma unroll
        for (int j = 0; j < 16; j++) {
            acc = __fadd_rn(acc, x[t * 16 + j]);
            inn[t * 16 + j] = acc;
        }
        u[t] = acc;
    }
    __syncthreads();
    if (t < 4) {
        float acc = 0.0f;
#pragma unroll
        for (int j = 0; j < 16; j++) {
            acc = __fadd_rn(acc, u[t * 16 + j]);
            m[t * 16 + j] = acc;
        }
        w[t] = acc;
    }
    __syncthreads();
    if (t == 0) {
        float acc = 0.0f;
#pragma unroll
        for (int c = 0; c < 4; c++) {
            float p = acc;
            acc = __fadd_rn(acc, w[c]);
            w[c] = p;
        }
    }
    __syncthreads();
    {
        int a = t >> 4;
        float off;
        if (a == 0) off = 0.0f;
        else {
            int b = a - 1;
            off = __fadd_rn(w[b >> 4], m[b]);
        }
        out[t] = __fadd_rn(off, inn[t]);
    }
    __syncthreads();
}

// ---------------------------------------------------------------------------
// Kernel 1: per-batch scans + fast trig. One 1024-thread block per batch.
// ---------------------------------------------------------------------------
__global__ __launch_bounds__(1024) void scan_kernel(
    const float* __restrict__ root_rvel,   // (NB, T)
    const float* __restrict__ root_vel)    // (NB, T, 2)
{
    __shared__ float sX[T];
    __shared__ float sO[T];
    __shared__ float sInn[T];
    __shared__ float sU[64];
    __shared__ float sM[64];
    __shared__ float sW[4];

    const int n = blockIdx.x;
    const int t = threadIdx.x;
    const int base = n * TP1;

    if (n == 0 && t == 0) g_fix_count = 0;   // stream-ordered reset

    // --- scan 1: yaw angle r ---
    sX[t] = root_rvel[n * T + t];
    rwr16_scan(t, sX, sO, sInn, sU, sM, sW);

    float r_excl = (t == 0) ? 0.0f : sO[t - 1];
    float r_last = sO[T - 1];

    float ch, sh;
    half_cs_fast(r_excl, ch, sh);
    g_rot[base + t] = make_float2(ch, sh);
    g_r[base + t] = r_excl;
    if (t == T - 1) {
        float c2, s2;
        half_cs_fast(r_last, c2, s2);
        g_rot[base + T] = make_float2(c2, s2);
        g_r[base + T] = r_last;
    }

    // --- world-frame velocity: quat sandwich q*(0,vx,0,vz)*conj(q) ----
    float vx = root_vel[(n * T + t) * 2 + 0];
    float vz = root_vel[(n * T + t) * 2 + 1];
    float tx = fA(fM(ch, vx), fM(sh, vz));
    float tz = fS(fM(ch, vz), fM(sh, vx));
    float wx = fA(fM(tx, ch), fM(tz, sh));
    float wz = fS(fM(tz, ch), fM(tx, sh));

    // --- scan 2: integrate wx ---
    __syncthreads();
    sX[t] = wx;
    rwr16_scan(t, sX, sO, sInn, sU, sM, sW);
    float pxe = (t == 0) ? 0.0f : sO[t - 1];
    float pxl = sO[T - 1];

    // --- scan 3: integrate wz ---
    __syncthreads();
    sX[t] = wz;
    rwr16_scan(t, sX, sO, sInn, sU, sM, sW);
    float pze = (t == 0) ? 0.0f : sO[t - 1];
    float pzl = sO[T - 1];

    g_pos[base + t] = make_float2(pxe, pze);
    if (t == T - 1) g_pos[base + T] = make_float2(pxl, pzl);
}

// ---------------------------------------------------------------------------
// 6D -> local quaternion (qw,qx,qy,qz): reference fp32 evaluation order.
// ---------------------------------------------------------------------------
__device__ __forceinline__ void local_quat(
    float a1x, float a1y, float a1z, float a2x, float a2y, float a2z,
    float& qw, float& qx, float& qy, float& qz)
{
    float n1 = __fsqrt_rn(fA(fA(fM(a1x, a1x), fM(a1y, a1y)), fM(a1z, a1z)));
    float b1x = fD(a1x, n1), b1y = fD(a1y, n1), b1z = fD(a1z, n1);

    float d = fA(fA(fM(b1x, a2x), fM(b1y, a2y)), fM(b1z, a2z));
    float ux = fS(a2x, fM(d, b1x));
    float uy = fS(a2y, fM(d, b1y));
    float uz = fS(a2z, fM(d, b1z));
    float n2 = __fsqrt_rn(fA(fA(fM(ux, ux), fM(uy, uy)), fM(uz, uz)));
    float b2x = fD(ux, n2), b2y = fD(uy, n2), b2z = fD(uz, n2);

    float b3x = fS(fM(b1y, b2z), fM(b1z, b2y));
    float b3y = fS(fM(b1z, b2x), fM(b1x, b2z));
    float b3z = fS(fM(b1x, b2y), fM(b1y, b2x));

    float m00 = b1x, m01 = b1y, m02 = b1z;
    float m10 = b2x, m11 = b2y, m12 = b2z;
    float m20 = b3x, m21 = b3y, m22 = b3z;

    float t0 = fA(fA(fA(1.0f, m00), m11), m22);
    float t1 = fS(fS(fA(1.0f, m00), m11), m22);
    float t2 = fS(fA(fS(1.0f, m00), m11), m22);
    float t3 = fA(fS(fS(1.0f, m00), m11), m22);
    float q0 = __fsqrt_rn(fmaxf(t0, 0.0f));
    float q1 = __fsqrt_rn(fmaxf(t1, 0.0f));
    float q2 = __fsqrt_rn(fmaxf(t2, 0.0f));
    float q3 = __fsqrt_rn(fmaxf(t3, 0.0f));

    int   idx  = 0;
    float best = q0;
    if (q1 > best) { best = q1; idx = 1; }
    if (q2 > best) { best = q2; idx = 2; }
    if (q3 > best) { best = q3; idx = 3; }

    float cw, cx, cy, cz;
    if (idx == 0) {
        cw = fM(q0, q0);    cx = fS(m21, m12);  cy = fS(m02, m20);  cz = fS(m10, m01);
    } else if (idx == 1) {
        cw = fS(m21, m12);  cx = fM(q1, q1);    cy = fA(m10, m01);  cz = fA(m02, m20);
    } else if (idx == 2) {
        cw = fS(m02, m20);  cx = fA(m10, m01);  cy = fM(q2, q2);    cz = fA(m21, m12);
    } else {
        cw = fS(m10, m01);  cx = fA(m20, m02);  cy = fA(m21, m12);  cz = fM(q3, q3);
    }
    float den = __fmul_rn(2.0f, fmaxf(best, 0.1f));
    qw = fD(cw, den); qx = fD(cx, den); qy = fD(cy, den); qz = fD(cz, den);
}

// ---------------------------------------------------------------------------
// Per-item math (fast path, no rescue): rot + pos.
// ---------------------------------------------------------------------------
__device__ __forceinline__ void item_math(
    float ch, float sh, float px, float pz,
    float a1x, float a1y, float a1z, float a2x, float a2y, float a2z,
    float vx, float vy, float vz,
    float& gx, float& gy, float& gz, float4& rot)
{
    float qw, qx, qy, qz;
    local_quat(a1x, a1y, a1z, a2x, a2y, a2z, qw, qx, qy, qz);

    float ow = fS(fM(ch, qw), fM(sh, qy));
    float ox = fA(fM(ch, qx), fM(sh, qz));
    float oy = fA(fM(ch, qy), fM(sh, qw));
    float oz = fS(fM(ch, qz), fM(sh, qx));
    if (ow < 0.0f) { ow = -ow; ox = -ox; oy = -oy; oz = -oz; }
    rot = make_float4(ow, ox, oy, oz);

    float tx = fA(fM(ch, vx), fM(sh, vz));
    float ty = fM(ch, vy);
    float tz = fS(fM(ch, vz), fM(sh, vx));
    float ox_p = fA(fM(tx, ch), fM(tz, sh));
    float oy_p = fA(fM(fM(sh, vy), sh), fM(ty, ch));  // + sh^2*vy (w-channel)
    float oz_p = fS(fM(tz, ch), fM(tx, sh));

    gx = fA(ox_p, px);
    gy = oy_p;
    gz = fA(oz_p, pz);
}

// ---------------------------------------------------------------------------
// Kernel 2: streaming phase, two items per thread (R11 shape), flag-only
// handling of sign-ambiguous items.
// ---------------------------------------------------------------------------
__global__ void __launch_bounds__(P2_THREADS, 6) phase2_kernel(
    const float* __restrict__ local_pos,   // (NB, TP1, J, 3)
    const float4* __restrict__ local_rot,  // (NB, TP1, J, 6) as float4s
    float2* __restrict__ out_pos,          // (NB, TP1, J, 3) as float2s
    float4* __restrict__ out_rot)          // (NB, TP1, J)
{
    unsigned int p = blockIdx.x * P2_THREADS + threadIdx.x;

    unsigned int i = 2u * p;
    unsigned int nt = i / J;

    float2 cs = g_rot[nt];
    float2 pp = g_pos[nt];

    const size_t pg = p;
    const float4* lr = local_rot + pg * 3;
    float4 A = lr[0], B = lr[1], C = lr[2];
    const float2* lp = (const float2*)(local_pos) + pg * 3;
    float2 P0 = lp[0], P1 = lp[1], P2 = lp[2];

    float gx0, gy0, gz0, gx1, gy1, gz1;
    float4 r0, r1;

    item_math(cs.x, cs.y, pp.x, pp.y,
              A.x, A.y, A.z, A.w, B.x, B.y,
              P0.x, P0.y, P1.x,
              gx0, gy0, gz0, r0);
    item_math(cs.x, cs.y, pp.x, pp.y,
              B.z, B.w, C.x, C.y, C.z, C.w,
              P1.y, P2.x, P2.y,
              gx1, gy1, gz1, r1);

    // post-standardize w == |ow|: flag sign-ambiguous items for exact fixup
    if (r0.x < 1e-4f) {
        unsigned int s = atomicAdd(&g_fix_count, 1u);
        if (s < FIX_CAP) g_fix[s] = i;
    }
    if (r1.x < 1e-4f) {
        unsigned int s = atomicAdd(&g_fix_count, 1u);
        if (s < FIX_CAP) g_fix[s] = i + 1;
    }

    float2* op = out_pos + pg * 3;
    op[0] = make_float2(gx0, gy0);
    op[1] = make_float2(gz0, gx1);
    op[2] = make_float2(gy1, gz1);

    out_rot[pg * 2]     = r0;
    out_rot[pg * 2 + 1] = r1;
}

// ---------------------------------------------------------------------------
// Kernel 3: exact fixup of flagged items (~hundreds). Recomputes the
// quaternion with correctly-rounded ch/sh (reference bits) and overwrites.
// ---------------------------------------------------------------------------
__global__ __launch_bounds__(256) void fixup_kernel(
    const float4* __restrict__ local_rot,  // (NB, TP1, J, 6) as float4s
    float4* __restrict__ out_rot)          // (NB, TP1, J)
{
    unsigned int k = blockIdx.x * 256 + threadIdx.x;
    unsigned int cnt = g_fix_count;
    if (cnt > FIX_CAP) cnt = FIX_CAP;
    if (k >= cnt) return;

    unsigned int i = g_fix[k];
    unsigned int nt = i / J;
    unsigned int p = i >> 1;
    bool second = (i & 1u) != 0u;

    float chc, shc;
    half_cs_exact(g_r[nt], chc, shc);

    const float4* lr = local_rot + (size_t)p * 3;
    float4 A = lr[0], B = lr[1], C = lr[2];

    float a1x, a1y, a1z, a2x, a2y, a2z;
    if (!second) { a1x = A.x; a1y = A.y; a1z = A.z; a2x = A.w; a2y = B.x; a2z = B.y; }
    else         { a1x = B.z; a1y = B.w; a1z = C.x; a2x = C.y; a2y = C.z; a2z = C.w; }

    float qw, qx, qy, qz;
    local_quat(a1x, a1y, a1z, a2x, a2y, a2z, qw, qx, qy, qz);

    float ow = fS(fM(chc, qw), fM(shc, qy));
    float ox = fA(fM(chc, qx), fM(shc, qz));
    float oy = fA(fM(chc, qy), fM(shc, qw));
    float oz = fS(fM(chc, qz), fM(shc, qx));
    if (ow < 0.0f) { ow = -ow; ox = -ox; oy = -oy; oz = -oz; }

    out_rot[i] = make_float4(ow, ox, oy, oz);
}

// ---------------------------------------------------------------------------
extern "C" void kernel_launch(void* const* d_in, const int* in_sizes, int n_in,
                              void* d_out, int out_size) {
    const float* root_rvel = (const float*)d_in[0];
    const float* local_pos = (const float*)d_in[1];
    const float* local_rot = (const float*)d_in[2];
    const float* root_vel  = (const float*)d_in[3];

    float*  out_pos = (float*)d_out;
    float4* out_rot = (float4*)((float*)d_out + POS_ELEMS);

    scan_kernel<<<NB, 1024>>>(root_rvel, root_vel);
    phase2_kernel<<<P2_BLOCKS, P2_THREADS>>>(local_pos,
                                             (const float4*)local_rot,
                                             (float2*)out_pos, out_rot);
    fixup_kernel<<<FIX_CAP / 256, 256>>>((const float4*)local_rot, out_rot);
}